// round 11
// baseline (speedup 1.0000x reference)
#include <cuda_runtime.h>
#include <cuda_fp16.h>
#include <math.h>
#include <stdint.h>

#define BB 16
#define TT 2048
#define DD 1024
#define MROWS (BB * TT)       // 32768
#define LN_EPS 1e-5f

// ---- common tiling ----
#define BM 128
#define BN 128
#define BK 64                  // fp16 elems per k-chunk (4 kk-steps of 16)
#define ROWB 144               // 128B data + 16B pad (conflict-free ldmatrix)
#define GROUP_M 16

// split-A (value) kernel: 256 threads, 2-stage
#define S_NTH 256
#define S_NSTAGE 2
#define S_A_HI 0
#define S_A_LO (BM * ROWB)
#define S_B_HI (2 * BM * ROWB)
#define S_STAGE (2 * BM * ROWB + BN * ROWB)      // 55296
#define S_SMEM (S_NSTAGE * S_STAGE)              // 110592

// single-A (gate / GEMM2) kernel: 128 threads, 64x64 warp tiles, 3-stage
#define G_NTH 128
#define G_NSTAGE 3
#define G_A 0
#define G_B (BM * ROWB)
#define G_STAGE (BM * ROWB + BN * ROWB)          // 36864
#define G_SMEM (G_NSTAGE * G_STAGE)              // 110592

// ---- scratch (__device__ globals; no cudaMalloc allowed) ----
__device__ __half g_xhi[(size_t)MROWS * DD];
__device__ __half g_xlo[(size_t)MROWS * DD];
__device__ __half g_wh [(size_t)2 * DD * DD];    // W_in fp16
__device__ __half g_sh [(size_t)DD * DD];        // W_state fp16
__device__ __half g_vhi[(size_t)MROWS * DD];     // vx fp16
__device__ __half g_ch [(size_t)MROWS * DD];     // cand fp16
__device__ __half g_y  [(size_t)MROWS * DD];     // y fp16
__device__ float g_u[(size_t)MROWS * DD];

// ============================ device helpers ============================
__device__ __forceinline__ uint32_t smem_u32(const void* p) {
    uint32_t a;
    asm("{ .reg .u64 t; cvta.to.shared.u64 t, %1; cvt.u32.u64 %0, t; }" : "=r"(a) : "l"(p));
    return a;
}
__device__ __forceinline__ void cp16(uint32_t dst, const void* src) {
    asm volatile("cp.async.cg.shared.global [%0], [%1], 16;" :: "r"(dst), "l"(src));
}
__device__ __forceinline__ void cp_commit() {
    asm volatile("cp.async.commit_group;" ::: "memory");
}
template <int N>
__device__ __forceinline__ void cp_wait() {
    asm volatile("cp.async.wait_group %0;" :: "n"(N) : "memory");
}
__device__ __forceinline__ void ldsm4(uint32_t* r, uint32_t a) {
    asm volatile("ldmatrix.sync.aligned.m8n8.x4.shared.b16 {%0,%1,%2,%3}, [%4];"
                 : "=r"(r[0]), "=r"(r[1]), "=r"(r[2]), "=r"(r[3]) : "r"(a));
}
__device__ __forceinline__ void mma16816(float* c, const uint32_t* a, const uint32_t* b) {
    asm volatile(
        "mma.sync.aligned.m16n8k16.row.col.f32.f16.f16.f32 "
        "{%0,%1,%2,%3},{%4,%5,%6,%7},{%8,%9},{%0,%1,%2,%3};"
        : "+f"(c[0]), "+f"(c[1]), "+f"(c[2]), "+f"(c[3])
        : "r"(a[0]), "r"(a[1]), "r"(a[2]), "r"(a[3]), "r"(b[0]), "r"(b[1]));
}

// ============================ conversions ============================
__global__ __launch_bounds__(256) void split_kernel(
    const float* __restrict__ src, __half* __restrict__ hi,
    __half* __restrict__ lo, int n)
{
    int i = (blockIdx.x * blockDim.x + threadIdx.x) * 4;
    if (i < n) {
        float4 v = *(const float4*)(src + i);
        float vv[4] = {v.x, v.y, v.z, v.w};
        unsigned short hb[4], lb[4];
#pragma unroll
        for (int e = 0; e < 4; e++) {
            __half h = __float2half_rn(vv[e]);
            float r = vv[e] - __half2float(h);
            hb[e] = __half_as_ushort(h);
            lb[e] = __half_as_ushort(__float2half_rn(r));
        }
        *(uint2*)(hi + i) = make_uint2((uint32_t)hb[0] | ((uint32_t)hb[1] << 16),
                                       (uint32_t)hb[2] | ((uint32_t)hb[3] << 16));
        *(uint2*)(lo + i) = make_uint2((uint32_t)lb[0] | ((uint32_t)lb[1] << 16),
                                       (uint32_t)lb[2] | ((uint32_t)lb[3] << 16));
    }
}

__global__ __launch_bounds__(256) void conv_kernel(
    const float* __restrict__ src, __half* __restrict__ dst, int n)
{
    int i = (blockIdx.x * blockDim.x + threadIdx.x) * 4;
    if (i < n) {
        float4 v = *(const float4*)(src + i);
        unsigned short hb[4];
        hb[0] = __half_as_ushort(__float2half_rn(v.x));
        hb[1] = __half_as_ushort(__float2half_rn(v.y));
        hb[2] = __half_as_ushort(__float2half_rn(v.z));
        hb[3] = __half_as_ushort(__float2half_rn(v.w));
        *(uint2*)(dst + i) = make_uint2((uint32_t)hb[0] | ((uint32_t)hb[1] << 16),
                                        (uint32_t)hb[2] | ((uint32_t)hb[3] << 16));
    }
}

// ============================ split-A GEMM (value half) ============================
// acc = Ahi@B^T + Alo@B^T ; output fp16 (vx). 8 warps = 4m x 2n, warp tile 32x64.
__global__ __launch_bounds__(S_NTH, 2)
void gemm_split(const __half* __restrict__ Ahi, const __half* __restrict__ Alo,
                const __half* __restrict__ Bh, __half* __restrict__ ohi, int ntn)
{
    extern __shared__ char smem[];
    const uint32_t sb = smem_u32(smem);
    const int tid = threadIdx.x;
    const int wid = tid >> 5, lane = tid & 31;

    int per_group = GROUP_M * ntn;
    int group = blockIdx.x / per_group;
    int rem = blockIdx.x % per_group;
    const int bm = (group * GROUP_M + (rem % GROUP_M)) * BM;
    const int bn = (rem / GROUP_M) * BN;

    const int wm = wid & 3;
    const int wn = wid >> 2;

    uint32_t offA[2], offB[4];
#pragma unroll
    for (int mf = 0; mf < 2; mf++)
        offA[mf] = (uint32_t)(wm * 32 + mf * 16 + (lane & 15)) * ROWB + (lane >> 4) * 16;
#pragma unroll
    for (int p = 0; p < 4; p++)
        offB[p] = (uint32_t)(wn * 64 + p * 16 + ((lane >> 4) & 1) * 8 + (lane & 7)) * ROWB
                  + ((lane >> 3) & 1) * 16;

    float acc[2][8][4];
#pragma unroll
    for (int a = 0; a < 2; a++)
#pragma unroll
        for (int b = 0; b < 8; b++)
#pragma unroll
            for (int e = 0; e < 4; e++) acc[a][b][e] = 0.f;

    auto load_half_s = [&](int kc, int half) {
        uint32_t base = sb + (uint32_t)(kc % S_NSTAGE) * S_STAGE;
        int k0 = kc * BK;
#pragma unroll
        for (int j = 0; j < 2; j++) {
            int ch = tid + (half * 2 + j) * S_NTH;
            int row = ch >> 3, kc8 = ch & 7;
            uint32_t doff = (uint32_t)row * ROWB + kc8 * 16;
            size_t ga = (size_t)(bm + row) * DD + k0 + kc8 * 8;
            cp16(base + S_A_HI + doff, Ahi + ga);
            cp16(base + S_A_LO + doff, Alo + ga);
            size_t gb = (size_t)(bn + row) * DD + k0 + kc8 * 8;
            cp16(base + S_B_HI + doff, Bh + gb);
        }
    };

    load_half_s(0, 0);
    load_half_s(0, 1);
    cp_commit();

    const int NKC = DD / BK;
    for (int kc = 0; kc < NKC; kc++) {
        cp_wait<0>();
        __syncthreads();
        uint32_t base = sb + (uint32_t)(kc % S_NSTAGE) * S_STAGE;
#pragma unroll
        for (int kk = 0; kk < 4; kk++) {
            uint32_t ah[2][4], al[2][4], bh[4][4];
#pragma unroll
            for (int mf = 0; mf < 2; mf++) {
                ldsm4(ah[mf], base + S_A_HI + offA[mf] + kk * 32);
                ldsm4(al[mf], base + S_A_LO + offA[mf] + kk * 32);
            }
#pragma unroll
            for (int p = 0; p < 4; p++)
                ldsm4(bh[p], base + S_B_HI + offB[p] + kk * 32);
            if (kc + 1 < NKC) {
                if (kk == 0) load_half_s(kc + 1, 0);
                if (kk == 1) { load_half_s(kc + 1, 1); cp_commit(); }
            }
#pragma unroll
            for (int mf = 0; mf < 2; mf++) {
#pragma unroll
                for (int nf = 0; nf < 8; nf++) {
                    const uint32_t* b2 = &bh[nf >> 1][(nf & 1) * 2];
                    mma16816(acc[mf][nf], ah[mf], b2);
                    mma16816(acc[mf][nf], al[mf], b2);
                }
            }
        }
    }

    const int r0 = bm + wm * 32 + (lane >> 2);
    const int c0 = bn + wn * 64 + (lane & 3) * 2;
#pragma unroll
    for (int mf = 0; mf < 2; mf++) {
        int r = r0 + mf * 16;
#pragma unroll
        for (int nf = 0; nf < 8; nf++) {
            int c = c0 + nf * 8;
            float* a = acc[mf][nf];
            __half2 h0 = __floats2half2_rn(a[0], a[1]);
            __half2 h1 = __floats2half2_rn(a[2], a[3]);
            *(__half2*)(ohi + (size_t)r * DD + c)       = h0;
            *(__half2*)(ohi + (size_t)(r + 8) * DD + c) = h1;
        }
    }
}

// ============================ single-A GEMM (gate / GEMM2) ============================
// 4 warps = 2m x 2n, warp tile 64x64, 3-stage. MODE 0: u=sigmoid(acc) fp32. MODE 1: fp16 out.
template <int MODE>
__global__ __launch_bounds__(G_NTH, 2)
void gemm_big(const __half* __restrict__ Ah, const __half* __restrict__ Bh,
              float* __restrict__ outF, __half* __restrict__ outH, int ntn)
{
    extern __shared__ char smem[];
    const uint32_t sb = smem_u32(smem);
    const int tid = threadIdx.x;
    const int wid = tid >> 5, lane = tid & 31;

    int per_group = GROUP_M * ntn;
    int group = blockIdx.x / per_group;
    int rem = blockIdx.x % per_group;
    const int bm = (group * GROUP_M + (rem % GROUP_M)) * BM;
    const int bn = (rem / GROUP_M) * BN;

    const int wm = wid & 1;   // 2 m-slices of 64
    const int wn = wid >> 1;  // 2 n-slices of 64

    uint32_t offA[4], offB[4];
#pragma unroll
    for (int mf = 0; mf < 4; mf++)
        offA[mf] = (uint32_t)(wm * 64 + mf * 16 + (lane & 15)) * ROWB + (lane >> 4) * 16;
#pragma unroll
    for (int p = 0; p < 4; p++)
        offB[p] = (uint32_t)(wn * 64 + p * 16 + ((lane >> 4) & 1) * 8 + (lane & 7)) * ROWB
                  + ((lane >> 3) & 1) * 16;

    float acc[4][8][4];
#pragma unroll
    for (int a = 0; a < 4; a++)
#pragma unroll
        for (int b = 0; b < 8; b++)
#pragma unroll
            for (int e = 0; e < 4; e++) acc[a][b][e] = 0.f;

    // per stage: A 1024 + B 1024 16B-chunks; 128 threads -> 16 cp/thread in 2 halves
    auto load_half_g = [&](int kc, int half) {
        uint32_t base = sb + (uint32_t)(kc % G_NSTAGE) * G_STAGE;
        int k0 = kc * BK;
#pragma unroll
        for (int j = 0; j < 4; j++) {
            int ch = tid + (half * 4 + j) * G_NTH;   // [0, 1024)
            int row = ch >> 3, kc8 = ch & 7;
            uint32_t doff = (uint32_t)row * ROWB + kc8 * 16;
            size_t ga = (size_t)(bm + row) * DD + k0 + kc8 * 8;
            cp16(base + G_A + doff, Ah + ga);
            size_t gb = (size_t)(bn + row) * DD + k0 + kc8 * 8;
            cp16(base + G_B + doff, Bh + gb);
        }
    };

    load_half_g(0, 0); load_half_g(0, 1); cp_commit();
    load_half_g(1, 0); load_half_g(1, 1); cp_commit();

    const int NKC = DD / BK;
    for (int kc = 0; kc < NKC; kc++) {
        cp_wait<1>();                      // stage kc complete (kc+1 may be in flight)
        __syncthreads();
        uint32_t base = sb + (uint32_t)(kc % G_NSTAGE) * G_STAGE;
#pragma unroll
        for (int kk = 0; kk < 4; kk++) {
            uint32_t ah[4][4], bh[4][4];
#pragma unroll
            for (int mf = 0; mf < 4; mf++)
                ldsm4(ah[mf], base + G_A + offA[mf] + kk * 32);
#pragma unroll
            for (int p = 0; p < 4; p++)
                ldsm4(bh[p], base + G_B + offB[p] + kk * 32);
            if (kc + 2 < NKC) {
                if (kk == 0) load_half_g(kc + 2, 0);
                if (kk == 1) { load_half_g(kc + 2, 1); cp_commit(); }
            }
#pragma unroll
            for (int mf = 0; mf < 4; mf++) {
#pragma unroll
                for (int nf = 0; nf < 8; nf++) {
                    const uint32_t* b2 = &bh[nf >> 1][(nf & 1) * 2];
                    mma16816(acc[mf][nf], ah[mf], b2);
                }
            }
        }
    }

    const int r0 = bm + wm * 64 + (lane >> 2);
    const int c0 = bn + wn * 64 + (lane & 3) * 2;
#pragma unroll
    for (int mf = 0; mf < 4; mf++) {
        int r = r0 + mf * 16;
#pragma unroll
        for (int nf = 0; nf < 8; nf++) {
            int c = c0 + nf * 8;
            float* a = acc[mf][nf];
            if (MODE == 0) {
                float2 s0, s1;
                s0.x = 1.f / (1.f + __expf(-a[0]));
                s0.y = 1.f / (1.f + __expf(-a[1]));
                s1.x = 1.f / (1.f + __expf(-a[2]));
                s1.y = 1.f / (1.f + __expf(-a[3]));
                *(float2*)(outF + (size_t)r * DD + c)       = s0;
                *(float2*)(outF + (size_t)(r + 8) * DD + c) = s1;
            } else {
                __half2 h0 = __floats2half2_rn(a[0], a[1]);
                __half2 h1 = __floats2half2_rn(a[2], a[3]);
                *(__half2*)(outH + (size_t)r * DD + c)       = h0;
                *(__half2*)(outH + (size_t)(r + 8) * DD + c) = h1;
            }
        }
    }
}

// ============================ scan (diagonal recurrence) ============================
// h_t = u*h + (1-u)*c. Reads g_u (fp32) + g_ch (fp16); writes g_y (fp16).
__global__ __launch_bounds__(256) void scan_kernel()
{
    int idx = blockIdx.x * blockDim.x + threadIdx.x;
    int b = idx >> 10;
    int d = idx & (DD - 1);
    const float* up = g_u + (size_t)b * TT * DD + d;
    const __half* cp = g_ch + (size_t)b * TT * DD + d;
    __half* yp = g_y + (size_t)b * TT * DD + d;
    float h = 0.f;
    for (int t = 0; t < TT; t += 16) {
        float uu[16], cc[16];
#pragma unroll
        for (int j = 0; j < 16; j++) {
            uu[j] = up[(size_t)(t + j) * DD];
            cc[j] = __half2float(cp[(size_t)(t + j) * DD]);
        }
#pragma unroll
        for (int j = 0; j < 16; j++) {
            h = fmaf(uu[j], h - cc[j], cc[j]);
            cc[j] = h;
        }
#pragma unroll
        for (int j = 0; j < 16; j++) yp[(size_t)(t + j) * DD] = __float2half_rn(cc[j]);
    }
}

// ============================ LayerNorm ============================
__global__ __launch_bounds__(256) void ln_kernel(const float* __restrict__ gamma,
                                                 const float* __restrict__ beta,
                                                 float* __restrict__ out)
{
    int row = blockIdx.x;
    int t = threadIdx.x;
    const __half2* yr = (const __half2*)(g_y + (size_t)row * DD);
    __half2 p0 = yr[t * 2], p1 = yr[t * 2 + 1];
    float2 f0 = __half22float2(p0), f1 = __half22float2(p1);
    float s = f0.x + f0.y + f1.x + f1.y;
    float q = f0.x * f0.x + f0.y * f0.y + f1.x * f1.x + f1.y * f1.y;

#pragma unroll
    for (int o = 16; o; o >>= 1) {
        s += __shfl_xor_sync(0xFFFFFFFFu, s, o);
        q += __shfl_xor_sync(0xFFFFFFFFu, q, o);
    }
    __shared__ float sw[8], qw[8];
    __shared__ float mu_s, inv_s;
    int w = t >> 5, l = t & 31;
    if (l == 0) { sw[w] = s; qw[w] = q; }
    __syncthreads();
    if (t == 0) {
        float S = 0.f, Q = 0.f;
#pragma unroll
        for (int i = 0; i < 8; i++) { S += sw[i]; Q += qw[i]; }
        float mu = S * (1.f / DD);
        float var = Q * (1.f / DD) - mu * mu;
        mu_s = mu;
        inv_s = rsqrtf(var + LN_EPS);
    }
    __syncthreads();
    float mu = mu_s, inv = inv_s;

    const float4* g4 = (const float4*)gamma;
    const float4* b4 = (const float4*)beta;
    float4 gv = g4[t], bv = b4[t];
    float4 o;
    o.x = (f0.x - mu) * inv * gv.x + bv.x;
    o.y = (f0.y - mu) * inv * gv.y + bv.y;
    o.z = (f1.x - mu) * inv * gv.z + bv.z;
    o.w = (f1.y - mu) * inv * gv.w + bv.w;
    ((float4*)(out + (size_t)row * DD))[t] = o;
}

// ============================ host ============================
extern "C" void kernel_launch(void* const* d_in, const int* in_sizes, int n_in,
                              void* d_out, int out_size)
{
    const float* x       = (const float*)d_in[0];
    const float* W_in    = (const float*)d_in[1];
    const float* W_state = (const float*)d_in[2];
    const float* gamma   = (const float*)d_in[3];
    const float* beta    = (const float*)d_in[4];
    float* out = (float*)d_out;

    void *pxh, *pxl, *pwh, *psh, *pvh, *pch, *pu;
    cudaGetSymbolAddress(&pxh, g_xhi); cudaGetSymbolAddress(&pxl, g_xlo);
    cudaGetSymbolAddress(&pwh, g_wh);  cudaGetSymbolAddress(&psh, g_sh);
    cudaGetSymbolAddress(&pvh, g_vhi); cudaGetSymbolAddress(&pch, g_ch);
    cudaGetSymbolAddress(&pu,  g_u);

    cudaFuncSetAttribute((const void*)gemm_split,   cudaFuncAttributeMaxDynamicSharedMemorySize, S_SMEM);
    cudaFuncSetAttribute((const void*)gemm_big<0>,  cudaFuncAttributeMaxDynamicSharedMemorySize, G_SMEM);
    cudaFuncSetAttribute((const void*)gemm_big<1>,  cudaFuncAttributeMaxDynamicSharedMemorySize, G_SMEM);

    // conversions
    { int n = MROWS * DD;  split_kernel<<<(n / 4 + 255) / 256, 256>>>(x, (__half*)pxh, (__half*)pxl, n); }
    { int n = 2 * DD * DD; conv_kernel<<<(n / 4 + 255) / 256, 256>>>(W_in, (__half*)pwh, n); }
    { int n = DD * DD;     conv_kernel<<<(n / 4 + 255) / 256, 256>>>(W_state, (__half*)psh, n); }

    const int ntm = MROWS / BM;        // 256
    const int ntn = DD / BN;           // 8

    // GEMM1 gate half: x @ W_in[0:D]^T -> u = sigmoid (fp32)
    gemm_big<0><<<ntm * ntn, G_NTH, G_SMEM>>>(
        (const __half*)pxh, (const __half*)pwh, (float*)pu, nullptr, ntn);

    // GEMM1 value half: (x_hi + x_lo) @ W_in[D:2D]^T -> vx fp16
    gemm_split<<<ntm * ntn, S_NTH, S_SMEM>>>(
        (const __half*)pxh, (const __half*)pxl, (const __half*)pwh + (size_t)DD * DD,
        (__half*)pvh, ntn);

    // GEMM2: vx @ W_state^T -> cand fp16
    gemm_big<1><<<ntm * ntn, G_NTH, G_SMEM>>>(
        (const __half*)pvh, (const __half*)psh, nullptr, (__half*)pch, ntn);

    // scan over T -> y fp16, then LN -> out fp32
    scan_kernel<<<(BB * DD) / 256, 256>>>();
    ln_kernel<<<MROWS, 256>>>(gamma, beta, out);
}